// round 1
// baseline (speedup 1.0000x reference)
#include <cuda_runtime.h>
#include <cstdint>

#define TPB 256

// ---------------------------------------------------------------------------
// out = sum_i x[i]*c[i]  +  sum_{i<j} x[i]*x[j]*c2[base(i) + (j-i-1)]
// where c2 = c + n, base(i) = i*(2n-1-i)/2  (row-major packed upper triangle).
// ---------------------------------------------------------------------------

__global__ void zero_out_kernel(float* out) {
    if (threadIdx.x == 0 && blockIdx.x == 0) out[0] = 0.0f;
}

__device__ __forceinline__ float warp_sum(float v) {
    #pragma unroll
    for (int o = 16; o > 0; o >>= 1) v += __shfl_down_sync(0xffffffffu, v, o);
    return v;
}

// Vector body of one triangular row.
//   cv  : aligned float4 pointer into the coeff row (after scalar head)
//   xv  : aligned float4 pointer such that xv[v] covers x[jb-s+4v .. +3]
//   S   : row-uniform shift (jb mod 4); the needed window x[j..j+3] is the
//         S-shifted concat of xv[v] and xv[v+1]. S is a template parameter so
//         the component selection is fully static (no local-array spills).
template <int S>
__device__ __forceinline__ void row_body(float4& acc4,
                                         const float4* __restrict__ cv,
                                         const float4* __restrict__ xv,
                                         int nvec, int t) {
    #pragma unroll 4
    for (int v = t; v < nvec; v += TPB) {
        float4 cc = __ldcs(cv + v);     // streaming: evict-first, keep x in L1
        float4 xa = __ldg(cv == nullptr ? xv : xv + v);  // (cv never null; keeps __ldg)
        float4 xw;
        if (S == 0) {
            xw = xa;
        } else {
            float4 xb = __ldg(xv + v + 1);
            if (S == 1)      xw = make_float4(xa.y, xa.z, xa.w, xb.x);
            else if (S == 2) xw = make_float4(xa.z, xa.w, xb.x, xb.y);
            else             xw = make_float4(xa.w, xb.x, xb.y, xb.z);
        }
        acc4.x = fmaf(cc.x, xw.x, acc4.x);
        acc4.y = fmaf(cc.y, xw.y, acc4.y);
        acc4.z = fmaf(cc.z, xw.z, acc4.z);
        acc4.w = fmaf(cc.w, xw.w, acc4.w);
    }
}

__global__ __launch_bounds__(TPB)
void ham_kernel(const float* __restrict__ x,
                const float* __restrict__ c,
                float* __restrict__ out,
                int n) {
    const int b = blockIdx.x;   // 0 .. n/2-1
    const int t = threadIdx.x;

    const float* c2 = c + n;
    float acc = 0.0f;

    // degree-1 terms: block b owns indices b and n-1-b (covers all, once)
    if (t == 0) {
        int i2 = n - 1 - b;
        acc += __ldg(x + b) * __ldg(c + b) + __ldg(x + i2) * __ldg(c + i2);
    }

    // rows b (length n-1-b) and n-1-b (length b): total exactly n-1 elements
    #pragma unroll
    for (int r = 0; r < 2; ++r) {
        const int i = (r == 0) ? b : (n - 1 - b);
        const int len = n - 1 - i;
        if (len <= 0) continue;

        const float xi = __ldg(x + i);
        const int base = (int)((long long)i * (2LL * n - 1 - i) / 2);
        const float* crow = c2 + base;

        // scalar head until coeff pointer is 16B aligned
        int head = (4 - (base & 3)) & 3;
        if (head > len) head = len;
        if (t < head)
            acc += xi * __ldg(x + i + 1 + t) * __ldg(crow + t);

        const int rem = len - head;
        int nvec = rem >> 2;
        int tail = rem & 3;
        const int jb = i + 1 + head;     // first j of the vector body
        const int s  = jb & 3;
        // when shifted (s>0) the last vector would read xv one float4 past the
        // needed window; retire it to the scalar tail to stay in-bounds.
        if (s != 0 && nvec > 0) { nvec -= 1; tail += 4; }

        const float4* cv = reinterpret_cast<const float4*>(crow + head);
        const float4* xv = reinterpret_cast<const float4*>(x + (jb - s));

        float4 acc4 = make_float4(0.f, 0.f, 0.f, 0.f);
        switch (s) {
            case 0: row_body<0>(acc4, cv, xv, nvec, t); break;
            case 1: row_body<1>(acc4, cv, xv, nvec, t); break;
            case 2: row_body<2>(acc4, cv, xv, nvec, t); break;
            default: row_body<3>(acc4, cv, xv, nvec, t); break;
        }
        acc += xi * ((acc4.x + acc4.y) + (acc4.z + acc4.w));

        // scalar tail (up to 7 elements)
        const int donec = head + 4 * nvec;
        const int jdone = jb + 4 * nvec;
        if (t < tail)
            acc += xi * __ldg(x + jdone + t) * __ldg(crow + donec + t);
    }

    // block reduction: warp shuffle -> smem -> warp 0 -> one atomic per block
    __shared__ float wsum[TPB / 32];
    float w = warp_sum(acc);
    if ((t & 31) == 0) wsum[t >> 5] = w;
    __syncthreads();
    if (t < 32) {
        float v = (t < TPB / 32) ? wsum[t] : 0.0f;
        v = warp_sum(v);
        if (t == 0) atomicAdd(out, v);
    }
}

extern "C" void kernel_launch(void* const* d_in, const int* in_sizes, int n_in,
                              void* d_out, int out_size) {
    const float* x = (const float*)d_in[0];
    const float* c = (const float*)d_in[1];
    float* out = (float*)d_out;
    const int n = in_sizes[0];   // 8192

    zero_out_kernel<<<1, 32>>>(out);
    ham_kernel<<<n / 2, TPB>>>(x, c, out, n);
}

// round 2
// speedup vs baseline: 1.0611x; 1.0611x over previous
#include <cuda_runtime.h>

#define TPB 256
#define NBLOCKS 912   // ~152 SMs * 6 resident blocks: single persistent wave

// ---------------------------------------------------------------------------
// out = sum_i x[i]*c[i]  +  sum_{i<j} x[i]*x[j]*c2[base(i) + (j-i-1)]
// where c2 = c + n, base(i) = i*(2n-1-i)/2  (row-major packed upper triangle).
// Block b processes triangular rows {b, n-1-b} (lengths sum to n-1 -> perfect
// balance), grid-strided so each block handles ~half/NBLOCKS row-pairs.
// ---------------------------------------------------------------------------

__global__ void zero_out_kernel(float* out) {
    if (threadIdx.x == 0 && blockIdx.x == 0) out[0] = 0.0f;
}

__device__ __forceinline__ float warp_sum(float v) {
    #pragma unroll
    for (int o = 16; o > 0; o >>= 1) v += __shfl_down_sync(0xffffffffu, v, o);
    return v;
}

// Static S-shifted window select: x[j..j+3] = shift of (xa, xb) by S floats.
template <int S>
__device__ __forceinline__ float4 shift_win(float4 xa, float4 xb) {
    if (S == 0) return xa;
    if (S == 1) return make_float4(xa.y, xa.z, xa.w, xb.x);
    if (S == 2) return make_float4(xa.z, xa.w, xb.x, xb.y);
    return make_float4(xa.w, xb.x, xb.y, xb.z);
}

// Vector body of one triangular row, 2-way batched for MLP.
template <int S>
__device__ __forceinline__ void row_body(float4& acc4,
                                         const float4* __restrict__ cv,
                                         const float4* __restrict__ xv,
                                         int nvec, int t) {
    int v = t;
    // two independent 16B coeff loads in flight per thread per iteration
    for (; v + TPB < nvec; v += 2 * TPB) {
        float4 c0 = __ldcs(cv + v);
        float4 c1 = __ldcs(cv + v + TPB);
        float4 a0 = __ldg(xv + v);
        float4 a1 = __ldg(xv + v + TPB);
        float4 w0, w1;
        if (S == 0) {
            w0 = a0; w1 = a1;
        } else {
            float4 b0 = __ldg(xv + v + 1);
            float4 b1 = __ldg(xv + v + TPB + 1);
            w0 = shift_win<S>(a0, b0);
            w1 = shift_win<S>(a1, b1);
        }
        acc4.x = fmaf(c0.x, w0.x, acc4.x);
        acc4.y = fmaf(c0.y, w0.y, acc4.y);
        acc4.z = fmaf(c0.z, w0.z, acc4.z);
        acc4.w = fmaf(c0.w, w0.w, acc4.w);
        acc4.x = fmaf(c1.x, w1.x, acc4.x);
        acc4.y = fmaf(c1.y, w1.y, acc4.y);
        acc4.z = fmaf(c1.z, w1.z, acc4.z);
        acc4.w = fmaf(c1.w, w1.w, acc4.w);
    }
    if (v < nvec) {
        float4 c0 = __ldcs(cv + v);
        float4 a0 = __ldg(xv + v);
        float4 w0;
        if (S == 0) {
            w0 = a0;
        } else {
            float4 b0 = __ldg(xv + v + 1);
            w0 = shift_win<S>(a0, b0);
        }
        acc4.x = fmaf(c0.x, w0.x, acc4.x);
        acc4.y = fmaf(c0.y, w0.y, acc4.y);
        acc4.z = fmaf(c0.z, w0.z, acc4.z);
        acc4.w = fmaf(c0.w, w0.w, acc4.w);
    }
}

__global__ __launch_bounds__(TPB, 6)
void ham_kernel(const float* __restrict__ x,
                const float* __restrict__ c,
                float* __restrict__ out,
                int n) {
    const int t = threadIdx.x;
    const float* c2 = c + n;
    const int half = n >> 1;
    float acc = 0.0f;

    for (int b = blockIdx.x; b < half; b += gridDim.x) {
        // degree-1 terms: row-pair b owns indices b and n-1-b
        if (t == 0) {
            int i2 = n - 1 - b;
            acc += __ldg(x + b) * __ldg(c + b) + __ldg(x + i2) * __ldg(c + i2);
        }

        #pragma unroll
        for (int r = 0; r < 2; ++r) {
            const int i = r ? (n - 1 - b) : b;
            const int len = n - 1 - i;
            if (len <= 0) continue;

            const float xi = __ldg(x + i);
            // i*(2n-1-i) < 2^27 for n=8192, product always even -> exact in int
            const int base = (i * (2 * n - 1 - i)) >> 1;
            const float* crow = c2 + base;

            // scalar head until coeff pointer is 16B aligned
            int head = (4 - (base & 3)) & 3;
            if (head > len) head = len;
            if (t < head)
                acc += xi * __ldg(x + i + 1 + t) * __ldg(crow + t);

            const int rem = len - head;
            int nvec = rem >> 2;
            int tail = rem & 3;
            const int jb = i + 1 + head;   // first j of the vector body
            const int s  = jb & 3;
            // shifted rows would read xv one float4 past the window on the
            // last vector; retire it to the scalar tail to stay in-bounds.
            if (s != 0 && nvec > 0) { nvec -= 1; tail += 4; }

            const float4* cv = reinterpret_cast<const float4*>(crow + head);
            const float4* xv = reinterpret_cast<const float4*>(x + (jb - s));

            float4 a4 = make_float4(0.f, 0.f, 0.f, 0.f);
            switch (s) {
                case 0: row_body<0>(a4, cv, xv, nvec, t); break;
                case 1: row_body<1>(a4, cv, xv, nvec, t); break;
                case 2: row_body<2>(a4, cv, xv, nvec, t); break;
                default: row_body<3>(a4, cv, xv, nvec, t); break;
            }
            acc += xi * ((a4.x + a4.y) + (a4.z + a4.w));

            // scalar tail (up to 7 elements)
            const int donec = head + 4 * nvec;
            const int jdone = jb + 4 * nvec;
            if (t < tail)
                acc += xi * __ldg(x + jdone + t) * __ldg(crow + donec + t);
        }
    }

    // one reduction + one atomic per block, after ALL row-pairs
    __shared__ float wsum[TPB / 32];
    float w = warp_sum(acc);
    if ((t & 31) == 0) wsum[t >> 5] = w;
    __syncthreads();
    if (t < 32) {
        float v = (t < TPB / 32) ? wsum[t] : 0.0f;
        v = warp_sum(v);
        if (t == 0) atomicAdd(out, v);
    }
}

extern "C" void kernel_launch(void* const* d_in, const int* in_sizes, int n_in,
                              void* d_out, int out_size) {
    const float* x = (const float*)d_in[0];
    const float* c = (const float*)d_in[1];
    float* out = (float*)d_out;
    const int n = in_sizes[0];   // 8192

    zero_out_kernel<<<1, 32>>>(out);
    int half = n >> 1;
    int blocks = NBLOCKS < half ? NBLOCKS : half;
    ham_kernel<<<blocks, TPB>>>(x, c, out, n);
}

// round 3
// speedup vs baseline: 1.2206x; 1.1504x over previous
#include <cuda_runtime.h>

#define TPB     256
#define NBLOCKS 912      // persistent: ~6 blocks/SM on 148-152 SMs
#define W       512      // column-strip width (= 2 * TPB)
#define H       16       // rows per tile

// ---------------------------------------------------------------------------
// out = sum_j x[j] * ( c1[j] + sum_{i<j} x[i] * c2[base(i) + (j-i-1)] )
// c2 = c + n, base(i) = i*(2n-1-i)/2  (row-major packed upper triangle).
//
// Tile (it, js): rows i in [it*H, it*H+H), columns j in [js*W, js*W+W).
// Thread t owns columns j_a = js*W + t and j_b = js*W + TPB + t, holding one
// register accumulator per column. The inner i-loop reads ONLY the coeff
// stream (coalesced LDG.32, evict-first) plus one uniform x[i] per row.
// ---------------------------------------------------------------------------

__global__ void zero_out_kernel(float* out) {
    if (threadIdx.x == 0 && blockIdx.x == 0) out[0] = 0.0f;
}

__device__ __forceinline__ float warp_sum(float v) {
    #pragma unroll
    for (int o = 16; o > 0; o >>= 1) v += __shfl_down_sync(0xffffffffu, v, o);
    return v;
}

__global__ __launch_bounds__(TPB, 6)
void ham_kernel(const float* __restrict__ x,
                const float* __restrict__ c,
                float* __restrict__ out,
                int n) {
    const int t = threadIdx.x;
    const float* c2 = c + n;

    const int nstrips = n / W;                       // 16 for n=8192
    const int ntiles  = (W / H / 2) * nstrips * (nstrips + 1); // 16*ns*(ns+1)

    float sum = 0.0f;

    for (int f = blockIdx.x; f < ntiles; f += gridDim.x) {
        // strip js: tiles-per-strip = (W/H)*(js+1) = 32*(js+1),
        // prefix(js) = 16*js*(js+1)
        int js = 0;
        while (js + 1 < nstrips && 16 * (js + 1) * (js + 2) <= f) js++;
        const int it = f - 16 * js * (js + 1);

        const int j0  = js * W;
        const int i0  = it * H;
        const int j_a = j0 + t;
        const int j_b = j0 + TPB + t;

        float acc0 = 0.0f, acc1 = 0.0f;
        if (it == 0) {                       // fold degree-1 terms in once
            acc0 = __ldg(c + j_a);
            acc1 = __ldg(c + j_b);
        }

        // rows valid while i < max j in strip:  i < (js+1)*W - 1
        int iend = i0 + H;
        const int ilim = (js + 1) * W - 1;
        if (iend > ilim) iend = ilim;

        const int base = (i0 * (2 * n - 1 - i0)) >> 1;   // < 2^27, exact
        const float* p = c2 + base + (j_a - i0 - 1);

        if (i0 + H <= j0) {
            // ---- clean path: whole tile strictly above diagonal ----
            #pragma unroll 1
            for (int i = i0; i + 4 <= iend; i += 4) {
                const int o1 = n - 2 - i;
                const int o2 = 2 * n - 5 - 2 * i;
                const int o3 = 3 * n - 9 - 3 * i;
                const float xi0 = __ldg(x + i);
                const float xi1 = __ldg(x + i + 1);
                const float xi2 = __ldg(x + i + 2);
                const float xi3 = __ldg(x + i + 3);
                // 8 independent streaming loads in flight
                const float a0 = __ldcs(p);
                const float b0 = __ldcs(p + TPB);
                const float a1 = __ldcs(p + o1);
                const float b1 = __ldcs(p + o1 + TPB);
                const float a2 = __ldcs(p + o2);
                const float b2 = __ldcs(p + o2 + TPB);
                const float a3 = __ldcs(p + o3);
                const float b3 = __ldcs(p + o3 + TPB);
                acc0 = fmaf(xi0, a0, acc0);  acc1 = fmaf(xi0, b0, acc1);
                acc0 = fmaf(xi1, a1, acc0);  acc1 = fmaf(xi1, b1, acc1);
                acc0 = fmaf(xi2, a2, acc0);  acc1 = fmaf(xi2, b2, acc1);
                acc0 = fmaf(xi3, a3, acc0);  acc1 = fmaf(xi3, b3, acc1);
                p += 4 * n - 14 - 4 * i;
            }
            // (H % 4 == 0 and clean tiles always run full H rows: no remainder)
        } else {
            // ---- diagonal path: predicate j > i per element ----
            for (int i = i0; i < iend; ++i) {
                const float xi = __ldg(x + i);
                float ca = 0.0f, cb = 0.0f;
                if (j_a > i) ca = __ldcs(p);
                if (j_b > i) cb = __ldcs(p + TPB);
                acc0 = fmaf(xi, ca, acc0);
                acc1 = fmaf(xi, cb, acc1);
                p += n - 2 - i;
            }
        }

        sum += acc0 * __ldg(x + j_a) + acc1 * __ldg(x + j_b);
    }

    // block reduction: warp shuffle -> smem -> warp 0 -> one atomic per block
    __shared__ float wsum[TPB / 32];
    float w = warp_sum(sum);
    if ((t & 31) == 0) wsum[t >> 5] = w;
    __syncthreads();
    if (t < 32) {
        float v = (t < TPB / 32) ? wsum[t] : 0.0f;
        v = warp_sum(v);
        if (t == 0) atomicAdd(out, v);
    }
}

extern "C" void kernel_launch(void* const* d_in, const int* in_sizes, int n_in,
                              void* d_out, int out_size) {
    const float* x = (const float*)d_in[0];
    const float* c = (const float*)d_in[1];
    float* out = (float*)d_out;
    const int n = in_sizes[0];   // 8192

    zero_out_kernel<<<1, 32>>>(out);
    ham_kernel<<<NBLOCKS, TPB>>>(x, c, out, n);
}